// round 4
// baseline (speedup 1.0000x reference)
#include <cuda_runtime.h>
#include <math.h>

// ---------------- problem constants ----------------
#define B_   8
#define C_   128
#define HW_  4096
#define NKV_ 256
#define RPE_N 16129     // 127*127

typedef unsigned long long ull;

// ---------------- f32x2 packed-FMA helpers ----------------
__device__ __forceinline__ ull ffma2(ull a, ull b, ull c) {
    ull d;
    asm("fma.rn.f32x2 %0, %1, %2, %3;" : "=l"(d) : "l"(a), "l"(b), "l"(c));
    return d;
}
__device__ __forceinline__ ull pack2(float lo, float hi) {
    ull r;
    asm("mov.b64 %0, {%1, %2};" : "=l"(r) : "f"(lo), "f"(hi));
    return r;
}
__device__ __forceinline__ ull packs(float v) { return pack2(v, v); }
__device__ __forceinline__ float2 unpack2(ull v) {
    float x, y;
    asm("mov.b64 {%0, %1}, %2;" : "=f"(x), "=f"(y) : "l"(v));
    return make_float2(x, y);
}

// ---------------- device scratch ----------------
__device__ float g_q  [B_ * C_ * HW_];
__device__ float g_ao [B_ * C_ * HW_];
__device__ float g_off[16 * 64 * NKV_];
__device__ float g_pos[16 * NKV_ * 2];
__device__ float g_dm [16 * NKV_];
__device__ float g_xs [B_ * C_ * NKV_];
__device__ float g_k  [B_ * C_ * NKV_];
__device__ float g_v  [B_ * C_ * NKV_];

// ---------------- 128x128 tile GEMM with f32x2 ----------------
__device__ __forceinline__ void gemm_tile(
    const float* __restrict__ A, const float* __restrict__ X,
    float* __restrict__ Y, int ld)
{
    extern __shared__ float sm[];
    float* a_sm = sm;           // [128][128]
    float* b_sm = sm + 16384;   // [128][128]
    int tid = threadIdx.x;

    for (int i = tid; i < 4096; i += 256)
        ((float4*)a_sm)[i] = ((const float4*)A)[i];
    for (int i = tid; i < 4096; i += 256) {
        int k = i >> 5, p4 = (i & 31) * 4;
        *(float4*)(b_sm + k * 128 + p4) = *(const float4*)(X + (size_t)k * ld + p4);
    }
    __syncthreads();

    int tr = tid >> 4, tc = tid & 15;
    int oc0 = tr * 8, p0 = tc * 8;
    ull acc[8][4];
#pragma unroll
    for (int i = 0; i < 8; i++)
#pragma unroll
        for (int j = 0; j < 4; j++) acc[i][j] = 0ull;

#pragma unroll 2
    for (int k = 0; k < 128; k += 2) {
        float2 a2[8];
#pragma unroll
        for (int i = 0; i < 8; i++)
            a2[i] = *(const float2*)&a_sm[(oc0 + i) * 128 + k];
        ulonglong2 b00 = *(const ulonglong2*)&b_sm[k * 128 + p0];
        ulonglong2 b01 = *(const ulonglong2*)&b_sm[k * 128 + p0 + 4];
        ulonglong2 b10 = *(const ulonglong2*)&b_sm[(k + 1) * 128 + p0];
        ulonglong2 b11 = *(const ulonglong2*)&b_sm[(k + 1) * 128 + p0 + 4];
        ull bb0[4] = {b00.x, b00.y, b01.x, b01.y};
        ull bb1[4] = {b10.x, b10.y, b11.x, b11.y};
#pragma unroll
        for (int i = 0; i < 8; i++) {
            ull aa0 = packs(a2[i].x);
            ull aa1 = packs(a2[i].y);
#pragma unroll
            for (int j = 0; j < 4; j++) acc[i][j] = ffma2(aa0, bb0[j], acc[i][j]);
#pragma unroll
            for (int j = 0; j < 4; j++) acc[i][j] = ffma2(aa1, bb1[j], acc[i][j]);
        }
    }
#pragma unroll
    for (int i = 0; i < 8; i++) {
        float* yr = Y + (size_t)(oc0 + i) * ld + p0;
        float2 r0 = unpack2(acc[i][0]), r1 = unpack2(acc[i][1]);
        float2 r2 = unpack2(acc[i][2]), r3 = unpack2(acc[i][3]);
        *(float4*)yr       = make_float4(r0.x, r0.y, r1.x, r1.y);
        *(float4*)(yr + 4) = make_float4(r2.x, r2.y, r3.x, r3.y);
    }
}

__global__ void __launch_bounds__(256) gemm128_kernel(
    const float* __restrict__ A, const float* __restrict__ X,
    float* __restrict__ Y, int ld, int ntiles)
{
    int b  = blockIdx.x / ntiles;
    int pb = (blockIdx.x % ntiles) * 128;
    gemm_tile(A, X + (size_t)b * 128 * ld + pb, Y + (size_t)b * 128 * ld + pb, ld);
}

__global__ void __launch_bounds__(256) gemm_kv_kernel(
    const float* __restrict__ wk, const float* __restrict__ wv)
{
    int sel = blockIdx.x >> 4;
    int r   = blockIdx.x & 15;
    int b   = r >> 1;
    int pb  = (r & 1) * 128;
    const float* A = sel ? wv : wk;
    float* Y = sel ? g_v : g_k;
    gemm_tile(A, g_xs + (size_t)b * 128 * NKV_ + pb, Y + (size_t)b * 128 * NKV_ + pb, NKV_);
}

// ---------------- depthwise 5x5 stride-4 pad-2 ----------------
__global__ void __launch_bounds__(256) dwconv_kernel(const float* __restrict__ w_dw)
{
    __shared__ float plane[4096];
    __shared__ float ws[25];
    int bid = blockIdx.x;
    int bg = bid >> 6, c = bid & 63;
    int b = bg >> 1, g = bg & 1;
    int tid = threadIdx.x;

    const float* src = g_q + ((size_t)(b * 128 + g * 64 + c)) * HW_;
    for (int i = tid; i < 1024; i += 256)
        ((float4*)plane)[i] = ((const float4*)src)[i];
    if (tid < 25) ws[tid] = w_dw[c * 25 + tid];
    __syncthreads();

    int i = tid >> 4, j = tid & 15;
    int y0 = 4 * i - 2, x0 = 4 * j - 2;
    float acc = 0.f;
#pragma unroll
    for (int u = 0; u < 5; u++) {
        int yy = y0 + u;
        if ((unsigned)yy < 64u) {
#pragma unroll
            for (int v = 0; v < 5; v++) {
                int xx = x0 + v;
                if ((unsigned)xx < 64u) acc += plane[yy * 64 + xx] * ws[u * 5 + v];
            }
        }
    }
    g_off[((size_t)(bg * 64 + c)) * NKV_ + tid] = acc;
}

// ---------------- LN(var-only) + GELU + 1x1 -> offsets/modulation ----------------
__global__ void __launch_bounds__(256) offhead_kernel(
    const float* __restrict__ ln_w, const float* __restrict__ w_off)
{
    int bg = blockIdx.x;
    int sp = threadIdx.x;
    const float* base = g_off + (size_t)bg * 64 * NKV_ + sp;
    float v[64];
    float s = 0.f, s2 = 0.f;
#pragma unroll
    for (int c = 0; c < 64; c++) {
        float t = base[c * NKV_];
        v[c] = t; s += t; s2 += t * t;
    }
    float mean = s * (1.f / 64.f);
    float var  = s2 * (1.f / 64.f) - mean * mean;
    float rstd = rsqrtf(var + 1e-5f);

    float o0 = 0.f, o1 = 0.f, o2 = 0.f;
#pragma unroll
    for (int c = 0; c < 64; c++) {
        float t = v[c] * rstd * __ldg(&ln_w[c]);
        float ge = 0.5f * t * (1.f + erff(t * 0.70710678118654752f));
        o0 += __ldg(&w_off[c]) * ge;
        o1 += __ldg(&w_off[64 + c]) * ge;
        o2 += __ldg(&w_off[128 + c]) * ge;
    }
    int i = sp >> 4, j = sp & 15;
    float ry = (float)(2 * i + 1) * (1.f / 16.f) - 1.f;
    float rx = (float)(2 * j + 1) * (1.f / 16.f) - 1.f;
    g_pos[bg * 512 + sp * 2]     = tanhf(o0) * (1.f / 16.f) + ry;
    g_pos[bg * 512 + sp * 2 + 1] = tanhf(o1) * (1.f / 16.f) + rx;
    g_dm [bg * 256 + sp]         = 1.f / (1.f + expf(-o2));
}

// ---------------- bilinear sample of x at deformed points ----------------
__global__ void __launch_bounds__(256) sample_kernel(const float* __restrict__ x)
{
    int blk = blockIdx.x;                // 256 = 16 bg x 16 nchunk
    int bg = blk >> 4;
    int n0 = (blk & 15) * 16;
    int b = bg >> 1, g = bg & 1;
    int c = threadIdx.x & 63;
    int ni = threadIdx.x >> 6;
    const float* plane = x + ((size_t)(b * 128 + g * 64 + c)) * HW_;
    for (int nn = ni; nn < 16; nn += 4) {
        int n = n0 + nn;
        float py_ = g_pos[bg * 512 + n * 2];
        float px_ = g_pos[bg * 512 + n * 2 + 1];
        float dmv = g_dm[bg * 256 + n];
        float gx = (px_ + 1.f) * 31.5f;
        float gy = (py_ + 1.f) * 31.5f;
        float x0f = floorf(gx), y0f = floorf(gy);
        float wx = gx - x0f, wy = gy - y0f;
        int ix0 = (int)x0f, iy0 = (int)y0f;
        float v00 = 0.f, v01 = 0.f, v10 = 0.f, v11 = 0.f;
        bool xin0 = (unsigned)ix0 < 64u, xin1 = (unsigned)(ix0 + 1) < 64u;
        bool yin0 = (unsigned)iy0 < 64u, yin1 = (unsigned)(iy0 + 1) < 64u;
        if (yin0) { int r = iy0 * 64;       if (xin0) v00 = plane[r + ix0]; if (xin1) v01 = plane[r + ix0 + 1]; }
        if (yin1) { int r = (iy0 + 1) * 64; if (xin0) v10 = plane[r + ix0]; if (xin1) v11 = plane[r + ix0 + 1]; }
        float top = v00 + (v01 - v00) * wx;
        float bot = v10 + (v11 - v10) * wx;
        float val = top + (bot - top) * wy;
        g_xs[((size_t)(b * 128 + g * 64 + c)) * NKV_ + n] = val * dmv;
    }
}

// ---------------- fused attention v2 ----------------
// smem layout (float indices)
#define SM2_RPE  0                        // 16129 (+3 pad)
#define SM2_K    16132                    // [32][256]
#define SM2_VS   (16132 + 8192)           // [256][36]  v transposed, stride 36
#define SM2_Q2   (SM2_VS + 9216)          // [64][33] float2 duplicated q
#define SM2_PT   (SM2_Q2 + 4224)          // [256][65]  scores transposed
#define SM2_POS  (SM2_PT + 16640)         // [256][2]
#define SM2_REDM (SM2_POS + 512)          // [8][64]
#define SM2_REDS (SM2_REDM + 512)         // [8][64]
#define ATTN2_FLOATS (SM2_REDS + 512)     // 55940 floats = 223760 B

__global__ void __launch_bounds__(512) attn_kernel(const float* __restrict__ rpe)
{
    extern __shared__ float sm[];
    float* rpe_sm = sm + SM2_RPE;
    float* k_sm   = sm + SM2_K;
    float* vs_sm  = sm + SM2_VS;
    float* pt_sm  = sm + SM2_PT;
    float* pos_sm = sm + SM2_POS;
    float* redm   = sm + SM2_REDM;
    float* reds   = sm + SM2_REDS;

    int tid = threadIdx.x;
    int bh    = blockIdx.x >> 5;
    int group = blockIdx.x & 31;
    int b = bh >> 2, h = bh & 3, g = h >> 1;

    // ---- per-head loads ----
    const float* rp = rpe + (size_t)h * RPE_N;
    for (int i = tid; i < RPE_N; i += 512) rpe_sm[i] = rp[i];

    const float* kb = g_k + ((size_t)(b * 128 + h * 32)) * NKV_;
    for (int i = tid; i < 2048; i += 512)
        ((float4*)k_sm)[i] = ((const float4*)kb)[i];

    const float* vb = g_v + ((size_t)(b * 128 + h * 32)) * NKV_;
    for (int i = tid; i < 8192; i += 512) {
        int c = i >> 8, n = i & 255;
        vs_sm[n * 36 + c] = vb[c * 256 + n];
    }
    pos_sm[tid] = g_pos[(size_t)(b * 2 + g) * 512 + tid];

    int w = tid >> 5, l = tid & 31;
    int q0 = w * 4;                 // QK mapping: warp = 4 queries
    int nb = l * 8;                 // lane = 8 contiguous keys
    int qw = ((w & 1) << 5) + l;    // bias/softmax/PV mapping: lane = query
    int kbk = w >> 1;               // key block (32 keys)
    int c0 = (w >> 1) * 4;          // PV channels
    const float scale = 0.17677669529663687f;

    for (int t = 0; t < 2; t++) {
        int tile = group * 2 + t;
        int qbase = tile * 64;
        __syncthreads();   // pT/q2 reuse from previous tile

        // q load, duplicated float2 for pack-free f32x2
        const float* qb = g_q + ((size_t)(b * 128 + h * 32)) * HW_ + qbase;
        float2* q2 = (float2*)(sm + SM2_Q2);
        for (int i = tid; i < 2048; i += 512) {
            int c = i >> 6, qi = i & 63;
            float v = qb[(size_t)c * HW_ + qi];
            q2[qi * 33 + c] = make_float2(v, v);
        }
        __syncthreads();

        // ---- QK ----
        ull acc[4][4];
#pragma unroll
        for (int i = 0; i < 4; i++)
#pragma unroll
            for (int j = 0; j < 4; j++) acc[i][j] = 0ull;

        const ull* q2u = (const ull*)(sm + SM2_Q2);
#pragma unroll 4
        for (int c = 0; c < 32; c++) {
            ulonglong2 k0 = *(const ulonglong2*)&k_sm[c * 256 + nb];
            ulonglong2 k1 = *(const ulonglong2*)&k_sm[c * 256 + nb + 4];
#pragma unroll
            for (int i = 0; i < 4; i++) {
                ull qq = q2u[(q0 + i) * 33 + c];
                acc[i][0] = ffma2(qq, k0.x, acc[i][0]);
                acc[i][1] = ffma2(qq, k0.y, acc[i][1]);
                acc[i][2] = ffma2(qq, k1.x, acc[i][2]);
                acc[i][3] = ffma2(qq, k1.y, acc[i][3]);
            }
        }
        // store scaled scores transposed: pT[n][q]
#pragma unroll
        for (int i = 0; i < 4; i++)
#pragma unroll
            for (int j = 0; j < 4; j++) {
                float2 f = unpack2(acc[i][j]);
                pt_sm[(nb + 2 * j) * 65 + q0 + i]     = f.x * scale;
                pt_sm[(nb + 2 * j + 1) * 65 + q0 + i] = f.y * scale;
            }
        __syncthreads();

        // ---- bias + softmax, lane = query (conflict-free) ----
        float qx = (float)(2 * qw + 1) * (1.f / 64.f) - 1.f;
        float qy = (float)(2 * tile + 1) * (1.f / 64.f) - 1.f;
        float mx = -1e30f;
#pragma unroll 4
        for (int j = 0; j < 32; j++) {
            int n = kbk * 32 + j;
            float s = pt_sm[n * 65 + qw];
            float py_ = pos_sm[2 * n], px_ = pos_sm[2 * n + 1];
            float gx = ((qx - px_) * 0.5f + 1.f) * 63.f;
            float gy = ((qy - py_) * 0.5f + 1.f) * 63.f;
            float x0f = floorf(gx), y0f = floorf(gy);
            float wx = gx - x0f, wy = gy - y0f;
            int ix0 = (int)x0f, iy0 = (int)y0f;
            float v00 = 0.f, v01 = 0.f, v10 = 0.f, v11 = 0.f;
            bool xin0 = (unsigned)ix0 < 127u, xin1 = (unsigned)(ix0 + 1) < 127u;
            bool yin0 = (unsigned)iy0 < 127u, yin1 = (unsigned)(iy0 + 1) < 127u;
            if (yin0) { int r = iy0 * 127;       if (xin0) v00 = rpe_sm[r + ix0]; if (xin1) v01 = rpe_sm[r + ix0 + 1]; }
            if (yin1) { int r = (iy0 + 1) * 127; if (xin0) v10 = rpe_sm[r + ix0]; if (xin1) v11 = rpe_sm[r + ix0 + 1]; }
            float top = v00 + (v01 - v00) * wx;
            float bot = v10 + (v11 - v10) * wx;
            s += top + (bot - top) * wy;
            pt_sm[n * 65 + qw] = s;
            mx = fmaxf(mx, s);
        }
        redm[kbk * 64 + qw] = mx;
        __syncthreads();

        float gmx = redm[qw];
#pragma unroll
        for (int k = 1; k < 8; k++) gmx = fmaxf(gmx, redm[k * 64 + qw]);
        float sum = 0.f;
#pragma unroll 4
        for (int j = 0; j < 32; j++) {
            int n = kbk * 32 + j;
            float e = __expf(pt_sm[n * 65 + qw] - gmx);
            pt_sm[n * 65 + qw] = e;
            sum += e;
        }
        reds[kbk * 64 + qw] = sum;
        __syncthreads();

        float tot = reds[qw];
#pragma unroll
        for (int k = 1; k < 8; k++) tot += reds[k * 64 + qw];
        float inv = 1.f / tot;

        // ---- PV: thread = query qw x channels c0..c0+3 ----
        ull o0 = 0ull, o1 = 0ull;
#pragma unroll 4
        for (int n = 0; n < 256; n++) {
            float pv = pt_sm[n * 65 + qw];
            ulonglong2 vv = *(const ulonglong2*)&vs_sm[n * 36 + c0];
            ull pp = packs(pv);
            o0 = ffma2(pp, vv.x, o0);
            o1 = ffma2(pp, vv.y, o1);
        }
        float2 fa = unpack2(o0), fb = unpack2(o1);
        float* aob = g_ao + ((size_t)(b * 128 + h * 32 + c0)) * HW_ + qbase + qw;
        aob[0]        = fa.x * inv;
        aob[HW_]      = fa.y * inv;
        aob[2 * HW_]  = fb.x * inv;
        aob[3 * HW_]  = fb.y * inv;
    }
}

// ---------------- launch ----------------
extern "C" void kernel_launch(void* const* d_in, const int* in_sizes, int n_in,
                              void* d_out, int out_size)
{
    const float* x     = (const float*)d_in[0];
    const float* w_dw  = (const float*)d_in[1];
    const float* ln_w  = (const float*)d_in[2];
    const float* w_off = (const float*)d_in[3];
    const float* wq    = (const float*)d_in[4];
    const float* wk    = (const float*)d_in[5];
    const float* wv    = (const float*)d_in[6];
    const float* wo    = (const float*)d_in[7];
    const float* rpe   = (const float*)d_in[8];
    float* out = (float*)d_out;

    float *gq, *gao;
    cudaGetSymbolAddress((void**)&gq, g_q);
    cudaGetSymbolAddress((void**)&gao, g_ao);

    cudaFuncSetAttribute(gemm128_kernel, cudaFuncAttributeMaxDynamicSharedMemorySize, 131072);
    cudaFuncSetAttribute(gemm_kv_kernel, cudaFuncAttributeMaxDynamicSharedMemorySize, 131072);
    cudaFuncSetAttribute(attn_kernel, cudaFuncAttributeMaxDynamicSharedMemorySize,
                         ATTN2_FLOATS * 4);

    gemm128_kernel<<<256, 256, 131072>>>(wq, x, gq, HW_, 32);
    dwconv_kernel<<<1024, 256>>>(w_dw);
    offhead_kernel<<<16, 256>>>(ln_w, w_off);
    sample_kernel<<<256, 256>>>(x);
    gemm_kv_kernel<<<32, 256, 131072>>>(wk, wv);
    attn_kernel<<<1024, 512, ATTN2_FLOATS * 4>>>(rpe);
    gemm128_kernel<<<256, 256, 131072>>>(wo, gao, out, HW_, 32);
}